// round 15
// baseline (speedup 1.0000x reference)
#include <cuda_runtime.h>
#include <cstdint>

// CapacityRouter: logits = x@W, top-2 routing with capacity masking.
// Outputs (concatenated float32): top_k_indices [N,2], top_k_weights [N,2],
// capacity_mask [N,2], expert_counters [64], num_dropped [1].

#define N_TOKENS 262144
#define HID      1024
#define NEXP     64
#define CAP      10240          // int(N*K/E * 1.25)
#define NBLK     2048           // N_TOKENS / 128
#define TWO_N    (2*N_TOKENS)
#define FOUR_N   (4*N_TOKENS)
#define SIX_N    (6*N_TOKENS)

typedef unsigned long long ull;

__device__ int g_hist[NBLK * NEXP];   // per-chunk expert histogram
__device__ int g_base[NBLK * NEXP];   // exclusive per-expert base per chunk

// ---- packed fp32x2 helpers (Blackwell 2x fp32 path) ----
__device__ __forceinline__ ull dupf(float a) {
    ull r; asm("mov.b64 %0, {%1, %1};" : "=l"(r) : "f"(a)); return r;
}
__device__ __forceinline__ void ffma2(ull& d, ull a, ull b) {
    asm("fma.rn.f32x2 %0, %1, %2, %0;" : "+l"(d) : "l"(a), "l"(b));
}
__device__ __forceinline__ ull lds1(unsigned a) {
    ull r; asm volatile("ld.shared.b64 %0, [%1];" : "=l"(r) : "r"(a)); return r;
}
__device__ __forceinline__ void lds2(ull& a, ull& b, unsigned addr) {
    asm volatile("ld.shared.v2.b64 {%0, %1}, [%2];" : "=l"(a), "=l"(b) : "r"(addr));
}
__device__ __forceinline__ void unpk(float& lo, float& hi, ull v) {
    asm("mov.b64 {%0, %1}, %2;" : "=f"(lo), "=f"(hi) : "l"(v));
}

// Dynamic smem layout (66048 bytes):
//  [0      .. 33280)  float xs[2][32][130]   (x tile, [k][token], pad 130)
//  [33280  .. 66048)  ull  wsd[2][32][64]    (W tile, pre-duplicated (w,w))
//  epilogue reuses offset 0 as float ls[128][66]
#define XS_BUF_B   16640   // 32*130*4
#define WSD_OFF_B  33280
#define WSD_BUF_B  16384   // 32*64*8
#define DSM_BYTES  66048

// ===================== Kernel 1: GEMM + top-2 + histogram =====================
// Block: 128 tokens x 64 experts, 256 threads. Warp w -> experts [8w,8w+8).
// Lane l -> token pairs {2l,2l+1} and {64+2l,64+2l+1} packed in f32x2 halves.
// K tiled by 32; double-buffered smem, one __syncthreads per stage.
__global__ void __launch_bounds__(256, 3)
k1_gemm_top2(const float* __restrict__ x, const float* __restrict__ W,
             float* __restrict__ out)
{
    extern __shared__ char dsm[];
    float* xs  = (float*)dsm;                      // [2][32][130]
    ull*   wsd = (ull*)(dsm + WSD_OFF_B);          // [2][32][64]
    float* ls  = (float*)dsm;                      // [128][66] (epilogue reuse)
    __shared__ int shist[64];

    const int tid  = threadIdx.x;
    const int lane = tid & 31;
    const int we   = (tid >> 5) * 8;               // warp's first expert
    const long long T0 = (long long)blockIdx.x * 128;
    const unsigned smem_u = (unsigned)__cvta_generic_to_shared(dsm);

    if (tid < 64) shist[tid] = 0;
    if (blockIdx.x == 0 && tid == 0) out[SIX_N + 64] = 524288.0f; // dropped init

    ull acc[16];                                   // [pair p][expert e]
    #pragma unroll
    for (int i = 0; i < 16; i++) acc[i] = 0ULL;

    const int kg = (tid & 7) * 4;    // x staging: k-subgroup
    const int tb = tid >> 3;         // x staging: base token (0..31)
    const int cg = (tid & 15) * 4;   // W staging: expert subgroup
    const int rb = tid >> 4;         // W staging: base k-row (0..15)

    float4 rx[4]; float4 rw[2];
    // prefetch stage 0 and stage it into buffer 0
    #pragma unroll
    for (int i = 0; i < 4; i++)
        rx[i] = *(const float4*)(x + (T0 + tb + 32 * i) * HID + kg);
    #pragma unroll
    for (int i = 0; i < 2; i++)
        rw[i] = *(const float4*)(W + (long long)(rb + 16 * i) * NEXP + cg);

    {
        #pragma unroll
        for (int i = 0; i < 4; i++) {
            int tk = tb + 32 * i;
            xs[(kg + 0) * 130 + tk] = rx[i].x;
            xs[(kg + 1) * 130 + tk] = rx[i].y;
            xs[(kg + 2) * 130 + tk] = rx[i].z;
            xs[(kg + 3) * 130 + tk] = rx[i].w;
        }
        #pragma unroll
        for (int i = 0; i < 2; i++) {
            ull* row = wsd + (rb + 16 * i) * 64 + cg;
            row[0] = dupf(rw[i].x); row[1] = dupf(rw[i].y);
            row[2] = dupf(rw[i].z); row[3] = dupf(rw[i].w);
        }
    }
    __syncthreads();

    for (int s = 0; s < 32; ++s) {
        const int cur = s & 1;
        // prefetch next stage (overlaps with compute)
        if (s < 31) {
            const long long ko = (long long)(s + 1) * 32;
            #pragma unroll
            for (int i = 0; i < 4; i++)
                rx[i] = *(const float4*)(x + (T0 + tb + 32 * i) * HID + ko + kg);
            #pragma unroll
            for (int i = 0; i < 2; i++)
                rw[i] = *(const float4*)(W + (ko + rb + 16 * i) * NEXP + cg);
        }

        // compute on buffer cur: per k, 2 LDS.b64 (token pairs), 4 LDS.v2.b64
        // (pre-dupped W broadcast), 16 FFMA2 — no MOVs.
        const unsigned xb = smem_u + (unsigned)(cur * XS_BUF_B) + (unsigned)(lane * 8);
        const unsigned wb = smem_u + WSD_OFF_B + (unsigned)(cur * WSD_BUF_B) + (unsigned)(we * 8);
        #pragma unroll 8
        for (int k = 0; k < 32; k++) {
            ull xp0 = lds1(xb + (unsigned)(k * 520));
            ull xp1 = lds1(xb + (unsigned)(k * 520) + 256u);
            ull w0, w1, w2, w3, w4, w5, w6, w7;
            unsigned wa = wb + (unsigned)(k * 512);
            lds2(w0, w1, wa);
            lds2(w2, w3, wa + 16u);
            lds2(w4, w5, wa + 32u);
            lds2(w6, w7, wa + 48u);
            ffma2(acc[0],  xp0, w0); ffma2(acc[1],  xp0, w1);
            ffma2(acc[2],  xp0, w2); ffma2(acc[3],  xp0, w3);
            ffma2(acc[4],  xp0, w4); ffma2(acc[5],  xp0, w5);
            ffma2(acc[6],  xp0, w6); ffma2(acc[7],  xp0, w7);
            ffma2(acc[8],  xp1, w0); ffma2(acc[9],  xp1, w1);
            ffma2(acc[10], xp1, w2); ffma2(acc[11], xp1, w3);
            ffma2(acc[12], xp1, w4); ffma2(acc[13], xp1, w5);
            ffma2(acc[14], xp1, w6); ffma2(acc[15], xp1, w7);
        }

        // stage next buffer
        if (s < 31) {
            float* xsn = xs + (cur ^ 1) * (XS_BUF_B / 4);
            ull*   wsn = wsd + (cur ^ 1) * (WSD_BUF_B / 8);
            #pragma unroll
            for (int i = 0; i < 4; i++) {
                int tk = tb + 32 * i;
                xsn[(kg + 0) * 130 + tk] = rx[i].x;
                xsn[(kg + 1) * 130 + tk] = rx[i].y;
                xsn[(kg + 2) * 130 + tk] = rx[i].z;
                xsn[(kg + 3) * 130 + tk] = rx[i].w;
            }
            #pragma unroll
            for (int i = 0; i < 2; i++) {
                ull* row = wsn + (rb + 16 * i) * 64 + cg;
                row[0] = dupf(rw[i].x); row[1] = dupf(rw[i].y);
                row[2] = dupf(rw[i].z); row[3] = dupf(rw[i].w);
            }
        }
        __syncthreads();
    }

    // exchange logits through smem: ls[token][expert], stride 66
    #pragma unroll
    for (int e = 0; e < 8; e++) {
        float a0, a1, b0, b1;
        unpk(a0, a1, acc[e]);       // tokens 2l, 2l+1
        unpk(b0, b1, acc[8 + e]);   // tokens 64+2l, 64+2l+1
        ls[(2 * lane) * 66 + we + e]       = a0;
        ls[(2 * lane + 1) * 66 + we + e]   = a1;
        ls[(64 + 2 * lane) * 66 + we + e]  = b0;
        ls[(64 + 2 * lane + 1) * 66 + we + e] = b1;
    }
    __syncthreads();

    if (tid < 128) {
        const float* row = ls + tid * 66;
        float v1 = -3.402823466e38f, v2 = -3.402823466e38f;
        int i1 = 0, i2 = 0;
        #pragma unroll
        for (int e = 0; e < NEXP; e++) {
            float v = row[e];
            if (v > v1)      { v2 = v1; i2 = i1; v1 = v; i1 = e; }
            else if (v > v2) { v2 = v;  i2 = e; }
        }
        // softmax monotonic; top-k ratio needs only the top-2 logits:
        // w1 = 1/(1+exp(l2-l1)), w2 = exp(l2-l1)*w1
        float e2 = expf(v2 - v1);
        float r  = 1.0f / (1.0f + e2);
        long long gt = T0 + tid;
        out[2 * gt]             = (float)i1;
        out[2 * gt + 1]         = (float)i2;
        out[TWO_N + 2 * gt]     = r;
        out[TWO_N + 2 * gt + 1] = e2 * r;
        atomicAdd(&shist[i1], 1);
        atomicAdd(&shist[i2], 1);
    }
    __syncthreads();
    if (tid < 64) g_hist[blockIdx.x * 64 + tid] = shist[tid];
}

// ============ Kernel 2: per-expert exclusive scan over chunks (parallel) ======
// 64 blocks (one per expert) x 256 threads; each thread scans 8 chunk rows.
__global__ void __launch_bounds__(256)
k2_scan(float* __restrict__ out)
{
    __shared__ int warp_tot[8];
    const int e = blockIdx.x;
    const int t = threadIdx.x;
    const int lane = t & 31, wid = t >> 5;

    int v[8];
    int s = 0;
    #pragma unroll
    for (int j = 0; j < 8; j++) {
        int h = g_hist[(t * 8 + j) * 64 + e];
        v[j] = s;            // exclusive within-thread prefix
        s += h;
    }
    // warp inclusive scan of thread totals
    int sc = s;
    #pragma unroll
    for (int o = 1; o < 32; o <<= 1) {
        int n = __shfl_up_sync(0xFFFFFFFFu, sc, o);
        if (lane >= o) sc += n;
    }
    if (lane == 31) warp_tot[wid] = sc;
    __syncthreads();
    int wbase = 0;
    #pragma unroll
    for (int w = 0; w < 8; w++) if (w < wid) wbase += warp_tot[w];
    const int tbase = wbase + sc - s;    // exclusive prefix for this thread

    #pragma unroll
    for (int j = 0; j < 8; j++)
        g_base[(t * 8 + j) * 64 + e] = tbase + v[j];

    if (t == 255) {
        int total = wbase + sc;          // grand total for expert e
        int kept = total < CAP ? total : CAP;
        out[SIX_N + e] = (float)kept;
        atomicAdd(&out[SIX_N + 64], -(float)kept);  // exact int-valued floats
    }
}

// ===================== Kernel 3: ordered capacity mask + weight finalize ======
__global__ void __launch_bounds__(256)
k3_mask(float* __restrict__ out)
{
    __shared__ int se[256];
    __shared__ int sbase[64];
    __shared__ unsigned char smk[256];
    const int b = blockIdx.x;
    const int tid = threadIdx.x;

    int e = (int)out[(long long)b * 256 + tid];   // indices exact in float
    se[tid] = e;
    if (tid < 64) sbase[tid] = g_base[b * 64 + tid];
    __syncthreads();

    // thread-per-expert ordered rank within the chunk (exact reference order)
    if (tid < 64) {
        int cnt = sbase[tid];
        #pragma unroll 4
        for (int i = 0; i < 256; i++) {
            if (se[i] == tid) { smk[i] = (cnt < CAP) ? 1 : 0; cnt++; }
        }
    }
    __syncthreads();

    if (tid < 128) {
        long long a = (long long)b * 256 + 2 * tid;
        float m0 = (float)smk[2 * tid];
        float m1 = (float)smk[2 * tid + 1];
        float w0 = out[TWO_N + a];
        float w1 = out[TWO_N + a + 1];
        float d = m0 + m1 + 1e-10f;
        out[TWO_N + a]      = w0 * m0 / d;
        out[TWO_N + a + 1]  = w1 * m1 / d;
        out[FOUR_N + a]     = m0;
        out[FOUR_N + a + 1] = m1;
    }
}

extern "C" void kernel_launch(void* const* d_in, const int* in_sizes, int n_in,
                              void* d_out, int out_size)
{
    const float* x = (const float*)d_in[0];
    const float* W = (const float*)d_in[1];
    if (n_in >= 2 && in_sizes[0] < in_sizes[1]) {  // safety: order by size
        const float* t = x; x = W; W = t;
    }
    float* out = (float*)d_out;

    cudaFuncSetAttribute(k1_gemm_top2,
                         cudaFuncAttributeMaxDynamicSharedMemorySize, DSM_BYTES);

    k1_gemm_top2<<<NBLK, 256, DSM_BYTES>>>(x, W, out);
    k2_scan<<<64, 256>>>(out);
    k3_mask<<<NBLK, 256>>>(out);
}

// round 16
// speedup vs baseline: 1.1248x; 1.1248x over previous
#include <cuda_runtime.h>
#include <cstdint>

// CapacityRouter: logits = x@W, top-2 routing with capacity masking.
// Outputs (concatenated float32): top_k_indices [N,2], top_k_weights [N,2],
// capacity_mask [N,2], expert_counters [64], num_dropped [1].

#define N_TOKENS 262144
#define HID      1024
#define NEXP     64
#define CAP      10240          // int(N*K/E * 1.25)
#define NBLK1    1024           // k1 blocks: 256 tokens each
#define NCHUNK   2048           // 128-token histogram chunks
#define TWO_N    (2*N_TOKENS)
#define FOUR_N   (4*N_TOKENS)
#define SIX_N    (6*N_TOKENS)

typedef unsigned long long ull;

__device__ int g_hist[NCHUNK * NEXP];   // per-chunk expert histogram
__device__ int g_base[NCHUNK * NEXP];   // exclusive per-expert base per chunk

// ---- packed fp32x2 helpers (Blackwell 2x fp32 path) ----
__device__ __forceinline__ ull dupf(float a) {
    ull r; asm("mov.b64 %0, {%1, %1};" : "=l"(r) : "f"(a)); return r;
}
__device__ __forceinline__ void ffma2(ull& d, ull a, ull b) {
    asm("fma.rn.f32x2 %0, %1, %2, %0;" : "+l"(d) : "l"(a), "l"(b));
}
__device__ __forceinline__ ull lds1(unsigned a) {
    ull r; asm volatile("ld.shared.b64 %0, [%1];" : "=l"(r) : "r"(a)); return r;
}
__device__ __forceinline__ void lds2(ull& a, ull& b, unsigned addr) {
    asm volatile("ld.shared.v2.b64 {%0, %1}, [%2];" : "=l"(a), "=l"(b) : "r"(addr));
}
__device__ __forceinline__ void unpk(float& lo, float& hi, ull v) {
    asm("mov.b64 {%0, %1}, %2;" : "=f"(lo), "=f"(hi) : "l"(v));
}

// Dynamic smem layout:
//  xs : float[2][16][258]   x tile transposed [k][token], stride 258
//       (S=258 => transpose STS conflict-free: bank = 8*(tid&3)+(tid>>2))
//  wsd: ull  [2][16][64]    W tile pre-duplicated (w,w)
//  epilogue reuses base as float ls[256][65]
#define XS_STRIDE  258
#define XS_ROW_B   (XS_STRIDE*4)          // 1032
#define XS_BUF_B   (16*XS_ROW_B)          // 16512
#define WSD_OFF_B  (2*XS_BUF_B)           // 33024
#define WSD_BUF_B  (16*64*8)              // 8192
#define LS_STRIDE  65
#define DSM_BYTES  (256*LS_STRIDE*4)      // 66560 > 49408 compute region

// ===================== Kernel 1: GEMM + top-2 + histogram =====================
// Block: 256 tokens x 64 experts, 256 threads. Warp w -> experts [8w,8w+8).
// Lane l -> tokens {4l..4l+3} and {128+4l..128+4l+3} as 4 f32x2 pairs.
// K tiled by 16; double-buffered smem, one __syncthreads per stage.
__global__ void __launch_bounds__(256, 2)
k1_gemm_top2(const float* __restrict__ x, const float* __restrict__ W,
             float* __restrict__ out)
{
    extern __shared__ char dsm[];
    float* xs  = (float*)dsm;                      // [2][16][258]
    ull*   wsd = (ull*)(dsm + WSD_OFF_B);          // [2][16][64]
    float* ls  = (float*)dsm;                      // [256][65] (epilogue reuse)
    __shared__ int shist[2][64];

    const int tid  = threadIdx.x;
    const int lane = tid & 31;
    const int we   = (tid >> 5) * 8;               // warp's first expert
    const long long T0 = (long long)blockIdx.x * 256;
    const unsigned smem_u = (unsigned)__cvta_generic_to_shared(dsm);

    if (tid < 128) shist[tid >> 6][tid & 63] = 0;
    if (blockIdx.x == 0 && tid == 0) out[SIX_N + 64] = 524288.0f; // dropped init

    ull acc[32];                                   // [pair p][expert e]
    #pragma unroll
    for (int i = 0; i < 32; i++) acc[i] = 0ULL;

    // staging roles
    const int a  = tid & 3;          // x: k-subgroup (4 floats)
    const int b  = tid >> 2;         // x: token base (0..63), slots +64c
    const int rb = tid >> 4;         // W: k-row (0..15)
    const int cg = (tid & 15) * 4;   // W: expert subgroup

    float4 rx[4]; float4 rw;
    // prefetch stage 0
    #pragma unroll
    for (int c = 0; c < 4; c++)
        rx[c] = *(const float4*)(x + (T0 + b + 64 * c) * HID + a * 4);
    rw = *(const float4*)(W + (long long)rb * NEXP + cg);

    // stage into buffer 0
    {
        #pragma unroll
        for (int c = 0; c < 4; c++) {
            int tk = b + 64 * c;
            xs[(a * 4 + 0) * XS_STRIDE + tk] = rx[c].x;
            xs[(a * 4 + 1) * XS_STRIDE + tk] = rx[c].y;
            xs[(a * 4 + 2) * XS_STRIDE + tk] = rx[c].z;
            xs[(a * 4 + 3) * XS_STRIDE + tk] = rx[c].w;
        }
        ull* row = wsd + rb * 64 + cg;
        row[0] = dupf(rw.x); row[1] = dupf(rw.y);
        row[2] = dupf(rw.z); row[3] = dupf(rw.w);
    }
    __syncthreads();

    for (int s = 0; s < 64; ++s) {
        const int cur = s & 1;
        // prefetch next stage (overlaps with compute)
        if (s < 63) {
            const long long ko = (long long)(s + 1) * 16;
            #pragma unroll
            for (int c = 0; c < 4; c++)
                rx[c] = *(const float4*)(x + (T0 + b + 64 * c) * HID + ko + a * 4);
            rw = *(const float4*)(W + (ko + rb) * NEXP + cg);
        }

        // compute on buffer cur: per k, 4 LDS.b64 (token pairs), 4 broadcast
        // LDS.v2.b64 (pre-dupped W), 32 FFMA2.
        const unsigned xb = smem_u + (unsigned)(cur * XS_BUF_B) + (unsigned)(lane * 16);
        const unsigned wb = smem_u + WSD_OFF_B + (unsigned)(cur * WSD_BUF_B)
                          + (unsigned)(we * 8);
        #pragma unroll 8
        for (int k = 0; k < 16; k++) {
            unsigned xa = xb + (unsigned)(k * XS_ROW_B);
            ull xp0 = lds1(xa);          // tokens 4l, 4l+1
            ull xp1 = lds1(xa + 8u);     // tokens 4l+2, 4l+3
            ull xp2 = lds1(xa + 512u);   // tokens 128+4l, 128+4l+1
            ull xp3 = lds1(xa + 520u);   // tokens 128+4l+2, 128+4l+3
            ull w0, w1, w2, w3, w4, w5, w6, w7;
            unsigned wa = wb + (unsigned)(k * 512);
            lds2(w0, w1, wa);
            lds2(w2, w3, wa + 16u);
            lds2(w4, w5, wa + 32u);
            lds2(w6, w7, wa + 48u);
            ffma2(acc[0],  xp0, w0); ffma2(acc[1],  xp0, w1);
            ffma2(acc[2],  xp0, w2); ffma2(acc[3],  xp0, w3);
            ffma2(acc[4],  xp0, w4); ffma2(acc[5],  xp0, w5);
            ffma2(acc[6],  xp0, w6); ffma2(acc[7],  xp0, w7);
            ffma2(acc[8],  xp1, w0); ffma2(acc[9],  xp1, w1);
            ffma2(acc[10], xp1, w2); ffma2(acc[11], xp1, w3);
            ffma2(acc[12], xp1, w4); ffma2(acc[13], xp1, w5);
            ffma2(acc[14], xp1, w6); ffma2(acc[15], xp1, w7);
            ffma2(acc[16], xp2, w0); ffma2(acc[17], xp2, w1);
            ffma2(acc[18], xp2, w2); ffma2(acc[19], xp2, w3);
            ffma2(acc[20], xp2, w4); ffma2(acc[21], xp2, w5);
            ffma2(acc[22], xp2, w6); ffma2(acc[23], xp2, w7);
            ffma2(acc[24], xp3, w0); ffma2(acc[25], xp3, w1);
            ffma2(acc[26], xp3, w2); ffma2(acc[27], xp3, w3);
            ffma2(acc[28], xp3, w4); ffma2(acc[29], xp3, w5);
            ffma2(acc[30], xp3, w6); ffma2(acc[31], xp3, w7);
        }

        // stage next buffer
        if (s < 63) {
            float* xsn = xs + (cur ^ 1) * (XS_BUF_B / 4);
            ull*   wsn = wsd + (cur ^ 1) * (WSD_BUF_B / 8);
            #pragma unroll
            for (int c = 0; c < 4; c++) {
                int tk = b + 64 * c;
                xsn[(a * 4 + 0) * XS_STRIDE + tk] = rx[c].x;
                xsn[(a * 4 + 1) * XS_STRIDE + tk] = rx[c].y;
                xsn[(a * 4 + 2) * XS_STRIDE + tk] = rx[c].z;
                xsn[(a * 4 + 3) * XS_STRIDE + tk] = rx[c].w;
            }
            ull* row = wsn + rb * 64 + cg;
            row[0] = dupf(rw.x); row[1] = dupf(rw.y);
            row[2] = dupf(rw.z); row[3] = dupf(rw.w);
        }
        __syncthreads();
    }

    // exchange logits through smem: ls[token][expert], stride 65
    #pragma unroll
    for (int e = 0; e < 8; e++) {
        #pragma unroll
        for (int p = 0; p < 4; p++) {
            float lo, hi;
            unpk(lo, hi, acc[p * 8 + e]);
            int tk = (p < 2) ? (4 * lane + 2 * p) : (128 + 4 * lane + 2 * (p - 2));
            ls[tk * LS_STRIDE + we + e]       = lo;
            ls[(tk + 1) * LS_STRIDE + we + e] = hi;
        }
    }
    __syncthreads();

    {
        const float* row = ls + tid * LS_STRIDE;
        float v1 = -3.402823466e38f, v2 = -3.402823466e38f;
        int i1 = 0, i2 = 0;
        #pragma unroll
        for (int e = 0; e < NEXP; e++) {
            float v = row[e];
            if (v > v1)      { v2 = v1; i2 = i1; v1 = v; i1 = e; }
            else if (v > v2) { v2 = v;  i2 = e; }
        }
        // softmax monotonic; top-k ratio needs only the top-2 logits:
        // w1 = 1/(1+exp(l2-l1)), w2 = exp(l2-l1)*w1
        float e2 = expf(v2 - v1);
        float r  = 1.0f / (1.0f + e2);
        long long gt = T0 + tid;
        out[2 * gt]             = (float)i1;
        out[2 * gt + 1]         = (float)i2;
        out[TWO_N + 2 * gt]     = r;
        out[TWO_N + 2 * gt + 1] = e2 * r;
        atomicAdd(&shist[tid >> 7][i1], 1);
        atomicAdd(&shist[tid >> 7][i2], 1);
    }
    __syncthreads();
    if (tid < 128)
        g_hist[(2 * blockIdx.x + (tid >> 6)) * 64 + (tid & 63)] =
            shist[tid >> 6][tid & 63];
}

// ============ Kernel 2: per-expert exclusive scan over chunks (parallel) ======
// 64 blocks (one per expert) x 256 threads; each thread scans 8 chunk rows.
__global__ void __launch_bounds__(256)
k2_scan(float* __restrict__ out)
{
    __shared__ int warp_tot[8];
    const int e = blockIdx.x;
    const int t = threadIdx.x;
    const int lane = t & 31, wid = t >> 5;

    int v[8];
    int s = 0;
    #pragma unroll
    for (int j = 0; j < 8; j++) {
        int h = g_hist[(t * 8 + j) * 64 + e];
        v[j] = s;            // exclusive within-thread prefix
        s += h;
    }
    // warp inclusive scan of thread totals
    int sc = s;
    #pragma unroll
    for (int o = 1; o < 32; o <<= 1) {
        int n = __shfl_up_sync(0xFFFFFFFFu, sc, o);
        if (lane >= o) sc += n;
    }
    if (lane == 31) warp_tot[wid] = sc;
    __syncthreads();
    int wbase = 0;
    #pragma unroll
    for (int w = 0; w < 8; w++) if (w < wid) wbase += warp_tot[w];
    const int tbase = wbase + sc - s;    // exclusive prefix for this thread

    #pragma unroll
    for (int j = 0; j < 8; j++)
        g_base[(t * 8 + j) * 64 + e] = tbase + v[j];

    if (t == 255) {
        int total = wbase + sc;          // grand total for expert e
        int kept = total < CAP ? total : CAP;
        out[SIX_N + e] = (float)kept;
        atomicAdd(&out[SIX_N + 64], -(float)kept);  // exact int-valued floats
    }
}

// ===================== Kernel 3: ordered capacity mask + weight finalize ======
__global__ void __launch_bounds__(256)
k3_mask(float* __restrict__ out)
{
    __shared__ int se[256];
    __shared__ int sbase[64];
    __shared__ unsigned char smk[256];
    const int b = blockIdx.x;
    const int tid = threadIdx.x;

    int e = (int)out[(long long)b * 256 + tid];   // indices exact in float
    se[tid] = e;
    if (tid < 64) sbase[tid] = g_base[b * 64 + tid];
    __syncthreads();

    // thread-per-expert ordered rank within the chunk (exact reference order)
    if (tid < 64) {
        int cnt = sbase[tid];
        #pragma unroll 4
        for (int i = 0; i < 256; i++) {
            if (se[i] == tid) { smk[i] = (cnt < CAP) ? 1 : 0; cnt++; }
        }
    }
    __syncthreads();

    if (tid < 128) {
        long long a = (long long)b * 256 + 2 * tid;
        float m0 = (float)smk[2 * tid];
        float m1 = (float)smk[2 * tid + 1];
        float w0 = out[TWO_N + a];
        float w1 = out[TWO_N + a + 1];
        float d = m0 + m1 + 1e-10f;
        out[TWO_N + a]      = w0 * m0 / d;
        out[TWO_N + a + 1]  = w1 * m1 / d;
        out[FOUR_N + a]     = m0;
        out[FOUR_N + a + 1] = m1;
    }
}

extern "C" void kernel_launch(void* const* d_in, const int* in_sizes, int n_in,
                              void* d_out, int out_size)
{
    const float* x = (const float*)d_in[0];
    const float* W = (const float*)d_in[1];
    if (n_in >= 2 && in_sizes[0] < in_sizes[1]) {  // safety: order by size
        const float* t = x; x = W; W = t;
    }
    float* out = (float*)d_out;

    cudaFuncSetAttribute(k1_gemm_top2,
                         cudaFuncAttributeMaxDynamicSharedMemorySize, DSM_BYTES);

    k1_gemm_top2<<<NBLK1, 256, DSM_BYTES>>>(x, W, out);
    k2_scan<<<64, 256>>>(out);
    k3_mask<<<NCHUNK, 256>>>(out);
}

// round 17
// speedup vs baseline: 1.1877x; 1.0559x over previous
#include <cuda_runtime.h>
#include <cstdint>

// CapacityRouter: logits = x@W, top-2 routing with capacity masking.
// Outputs (concatenated float32): top_k_indices [N,2], top_k_weights [N,2],
// capacity_mask [N,2], expert_counters [64], num_dropped [1].

#define N_TOKENS 262144
#define HID      1024
#define NEXP     64
#define CAP      10240          // int(N*K/E * 1.25)
#define NBLK1    1024           // k1 blocks: 256 tokens each
#define NCHUNK   2048           // 128-token histogram chunks
#define TWO_N    (2*N_TOKENS)
#define FOUR_N   (4*N_TOKENS)
#define SIX_N    (6*N_TOKENS)

typedef unsigned long long ull;

__device__ int g_hist[NCHUNK * NEXP];   // per-chunk expert histogram
__device__ int g_base[NCHUNK * NEXP];   // exclusive per-expert base per chunk

// ---- packed fp32x2 helpers (Blackwell 2x fp32 path) ----
__device__ __forceinline__ ull dupf(float a) {
    ull r; asm("mov.b64 %0, {%1, %1};" : "=l"(r) : "f"(a)); return r;
}
__device__ __forceinline__ void ffma2(ull& d, ull a, ull b) {
    asm("fma.rn.f32x2 %0, %1, %2, %0;" : "+l"(d) : "l"(a), "l"(b));
}
__device__ __forceinline__ ull lds1(unsigned a) {
    ull r; asm volatile("ld.shared.b64 %0, [%1];" : "=l"(r) : "r"(a)); return r;
}
__device__ __forceinline__ void lds2(ull& a, ull& b, unsigned addr) {
    asm volatile("ld.shared.v2.b64 {%0, %1}, [%2];" : "=l"(a), "=l"(b) : "r"(addr));
}
__device__ __forceinline__ void unpk(float& lo, float& hi, ull v) {
    asm("mov.b64 {%0, %1}, %2;" : "=f"(lo), "=f"(hi) : "l"(v));
}

// Dynamic smem layout:
//  xs : float[2][16][258]   x tile transposed [k][token], stride 258
//       (258 % 32 == 2 => transpose STS is conflict-free; 258 even keeps
//        8B alignment for paired compute loads at byte offset lane*8 + 256p,
//        which are fully coalesced: 2 wavefronts, zero bank conflicts)
//  wsd: ull  [2][16][64]    W tile pre-duplicated (w,w)
//  epilogue reuses base as float ls[256][65]
#define XS_STRIDE  258
#define XS_ROW_B   (XS_STRIDE*4)          // 1032
#define XS_BUF_B   (16*XS_ROW_B)          // 16512
#define WSD_OFF_B  (2*XS_BUF_B)           // 33024
#define WSD_BUF_B  (16*64*8)              // 8192
#define LS_STRIDE  65
#define DSM_BYTES  (256*LS_STRIDE*4)      // 66560 > 49408 compute region

// ===================== Kernel 1: GEMM + top-2 + histogram =====================
// Block: 256 tokens x 64 experts, 256 threads. Warp w -> experts [8w,8w+8).
// Lane l -> token pairs {64p+2l, 64p+2l+1}, p=0..3 (coalesced 8B smem loads).
// K tiled by 16; double-buffered smem, one __syncthreads per stage.
__global__ void __launch_bounds__(256, 2)
k1_gemm_top2(const float* __restrict__ x, const float* __restrict__ W,
             float* __restrict__ out)
{
    extern __shared__ char dsm[];
    float* xs  = (float*)dsm;                      // [2][16][258]
    ull*   wsd = (ull*)(dsm + WSD_OFF_B);          // [2][16][64]
    float* ls  = (float*)dsm;                      // [256][65] (epilogue reuse)
    __shared__ int shist[2][64];

    const int tid  = threadIdx.x;
    const int lane = tid & 31;
    const int we   = (tid >> 5) * 8;               // warp's first expert
    const long long T0 = (long long)blockIdx.x * 256;
    const unsigned smem_u = (unsigned)__cvta_generic_to_shared(dsm);

    if (tid < 128) shist[tid >> 6][tid & 63] = 0;
    if (blockIdx.x == 0 && tid == 0) out[SIX_N + 64] = 524288.0f; // dropped init

    ull acc[32];                                   // [pair p][expert e]
    #pragma unroll
    for (int i = 0; i < 32; i++) acc[i] = 0ULL;

    // staging roles
    const int a  = tid & 3;          // x: k-subgroup (4 floats)
    const int b  = tid >> 2;         // x: token base (0..63), slots +64c
    const int rb = tid >> 4;         // W: k-row (0..15)
    const int cg = (tid & 15) * 4;   // W: expert subgroup

    float4 rx[4]; float4 rw;
    // prefetch stage 0
    #pragma unroll
    for (int c = 0; c < 4; c++)
        rx[c] = *(const float4*)(x + (T0 + b + 64 * c) * HID + a * 4);
    rw = *(const float4*)(W + (long long)rb * NEXP + cg);

    // stage into buffer 0
    {
        #pragma unroll
        for (int c = 0; c < 4; c++) {
            int tk = b + 64 * c;
            xs[(a * 4 + 0) * XS_STRIDE + tk] = rx[c].x;
            xs[(a * 4 + 1) * XS_STRIDE + tk] = rx[c].y;
            xs[(a * 4 + 2) * XS_STRIDE + tk] = rx[c].z;
            xs[(a * 4 + 3) * XS_STRIDE + tk] = rx[c].w;
        }
        ull* row = wsd + rb * 64 + cg;
        row[0] = dupf(rw.x); row[1] = dupf(rw.y);
        row[2] = dupf(rw.z); row[3] = dupf(rw.w);
    }
    __syncthreads();

    for (int s = 0; s < 64; ++s) {
        const int cur = s & 1;
        // prefetch next stage (overlaps with compute)
        if (s < 63) {
            const long long ko = (long long)(s + 1) * 16;
            #pragma unroll
            for (int c = 0; c < 4; c++)
                rx[c] = *(const float4*)(x + (T0 + b + 64 * c) * HID + ko + a * 4);
            rw = *(const float4*)(W + (ko + rb) * NEXP + cg);
        }

        // compute on buffer cur: per k, 4 coalesced LDS.b64 (token pairs at
        // byte lane*8 + 256p: 2 wavefronts each, conflict-free), 4 broadcast
        // LDS.v2.b64 (pre-dupped W), 32 FFMA2.
        const unsigned xb = smem_u + (unsigned)(cur * XS_BUF_B) + (unsigned)(lane * 8);
        const unsigned wb = smem_u + WSD_OFF_B + (unsigned)(cur * WSD_BUF_B)
                          + (unsigned)(we * 8);
        #pragma unroll 8
        for (int k = 0; k < 16; k++) {
            unsigned xa = xb + (unsigned)(k * XS_ROW_B);
            ull xp0 = lds1(xa);          // tokens 2l,   2l+1
            ull xp1 = lds1(xa + 256u);   // tokens 64+2l,  64+2l+1
            ull xp2 = lds1(xa + 512u);   // tokens 128+2l, 128+2l+1
            ull xp3 = lds1(xa + 768u);   // tokens 192+2l, 192+2l+1
            ull w0, w1, w2, w3, w4, w5, w6, w7;
            unsigned wa = wb + (unsigned)(k * 512);
            lds2(w0, w1, wa);
            lds2(w2, w3, wa + 16u);
            lds2(w4, w5, wa + 32u);
            lds2(w6, w7, wa + 48u);
            ffma2(acc[0],  xp0, w0); ffma2(acc[1],  xp0, w1);
            ffma2(acc[2],  xp0, w2); ffma2(acc[3],  xp0, w3);
            ffma2(acc[4],  xp0, w4); ffma2(acc[5],  xp0, w5);
            ffma2(acc[6],  xp0, w6); ffma2(acc[7],  xp0, w7);
            ffma2(acc[8],  xp1, w0); ffma2(acc[9],  xp1, w1);
            ffma2(acc[10], xp1, w2); ffma2(acc[11], xp1, w3);
            ffma2(acc[12], xp1, w4); ffma2(acc[13], xp1, w5);
            ffma2(acc[14], xp1, w6); ffma2(acc[15], xp1, w7);
            ffma2(acc[16], xp2, w0); ffma2(acc[17], xp2, w1);
            ffma2(acc[18], xp2, w2); ffma2(acc[19], xp2, w3);
            ffma2(acc[20], xp2, w4); ffma2(acc[21], xp2, w5);
            ffma2(acc[22], xp2, w6); ffma2(acc[23], xp2, w7);
            ffma2(acc[24], xp3, w0); ffma2(acc[25], xp3, w1);
            ffma2(acc[26], xp3, w2); ffma2(acc[27], xp3, w3);
            ffma2(acc[28], xp3, w4); ffma2(acc[29], xp3, w5);
            ffma2(acc[30], xp3, w6); ffma2(acc[31], xp3, w7);
        }

        // stage next buffer
        if (s < 63) {
            float* xsn = xs + (cur ^ 1) * (XS_BUF_B / 4);
            ull*   wsn = wsd + (cur ^ 1) * (WSD_BUF_B / 8);
            #pragma unroll
            for (int c = 0; c < 4; c++) {
                int tk = b + 64 * c;
                xsn[(a * 4 + 0) * XS_STRIDE + tk] = rx[c].x;
                xsn[(a * 4 + 1) * XS_STRIDE + tk] = rx[c].y;
                xsn[(a * 4 + 2) * XS_STRIDE + tk] = rx[c].z;
                xsn[(a * 4 + 3) * XS_STRIDE + tk] = rx[c].w;
            }
            ull* row = wsn + rb * 64 + cg;
            row[0] = dupf(rw.x); row[1] = dupf(rw.y);
            row[2] = dupf(rw.z); row[3] = dupf(rw.w);
        }
        __syncthreads();
    }

    // exchange logits through smem: ls[token][expert], stride 65
    #pragma unroll
    for (int e = 0; e < 8; e++) {
        #pragma unroll
        for (int p = 0; p < 4; p++) {
            float lo, hi;
            unpk(lo, hi, acc[p * 8 + e]);
            int tk = 64 * p + 2 * lane;
            ls[tk * LS_STRIDE + we + e]       = lo;
            ls[(tk + 1) * LS_STRIDE + we + e] = hi;
        }
    }
    __syncthreads();

    {
        const float* row = ls + tid * LS_STRIDE;
        float v1 = -3.402823466e38f, v2 = -3.402823466e38f;
        int i1 = 0, i2 = 0;
        #pragma unroll
        for (int e = 0; e < NEXP; e++) {
            float v = row[e];
            if (v > v1)      { v2 = v1; i2 = i1; v1 = v; i1 = e; }
            else if (v > v2) { v2 = v;  i2 = e; }
        }
        // softmax monotonic; top-k ratio needs only the top-2 logits:
        // w1 = 1/(1+exp(l2-l1)), w2 = exp(l2-l1)*w1
        float e2 = expf(v2 - v1);
        float r  = 1.0f / (1.0f + e2);
        long long gt = T0 + tid;
        out[2 * gt]             = (float)i1;
        out[2 * gt + 1]         = (float)i2;
        out[TWO_N + 2 * gt]     = r;
        out[TWO_N + 2 * gt + 1] = e2 * r;
        atomicAdd(&shist[tid >> 7][i1], 1);
        atomicAdd(&shist[tid >> 7][i2], 1);
    }
    __syncthreads();
    if (tid < 128)
        g_hist[(2 * blockIdx.x + (tid >> 6)) * 64 + (tid & 63)] =
            shist[tid >> 6][tid & 63];
}

// ============ Kernel 2: per-expert exclusive scan over chunks (parallel) ======
// 64 blocks (one per expert) x 256 threads; each thread scans 8 chunk rows.
__global__ void __launch_bounds__(256)
k2_scan(float* __restrict__ out)
{
    __shared__ int warp_tot[8];
    const int e = blockIdx.x;
    const int t = threadIdx.x;
    const int lane = t & 31, wid = t >> 5;

    int v[8];
    int s = 0;
    #pragma unroll
    for (int j = 0; j < 8; j++) {
        int h = g_hist[(t * 8 + j) * 64 + e];
        v[j] = s;            // exclusive within-thread prefix
        s += h;
    }
    // warp inclusive scan of thread totals
    int sc = s;
    #pragma unroll
    for (int o = 1; o < 32; o <<= 1) {
        int n = __shfl_up_sync(0xFFFFFFFFu, sc, o);
        if (lane >= o) sc += n;
    }
    if (lane == 31) warp_tot[wid] = sc;
    __syncthreads();
    int wbase = 0;
    #pragma unroll
    for (int w = 0; w < 8; w++) if (w < wid) wbase += warp_tot[w];
    const int tbase = wbase + sc - s;    // exclusive prefix for this thread

    #pragma unroll
    for (int j = 0; j < 8; j++)
        g_base[(t * 8 + j) * 64 + e] = tbase + v[j];

    if (t == 255) {
        int total = wbase + sc;          // grand total for expert e
        int kept = total < CAP ? total : CAP;
        out[SIX_N + e] = (float)kept;
        atomicAdd(&out[SIX_N + 64], -(float)kept);  // exact int-valued floats
    }
}

// ===================== Kernel 3: ordered capacity mask + weight finalize ======
__global__ void __launch_bounds__(256)
k3_mask(float* __restrict__ out)
{
    __shared__ int se[256];
    __shared__ int sbase[64];
    __shared__ unsigned char smk[256];
    const int b = blockIdx.x;
    const int tid = threadIdx.x;

    int e = (int)out[(long long)b * 256 + tid];   // indices exact in float
    se[tid] = e;
    if (tid < 64) sbase[tid] = g_base[b * 64 + tid];
    __syncthreads();

    // thread-per-expert ordered rank within the chunk (exact reference order)
    if (tid < 64) {
        int cnt = sbase[tid];
        #pragma unroll 4
        for (int i = 0; i < 256; i++) {
            if (se[i] == tid) { smk[i] = (cnt < CAP) ? 1 : 0; cnt++; }
        }
    }
    __syncthreads();

    if (tid < 128) {
        long long a = (long long)b * 256 + 2 * tid;
        float m0 = (float)smk[2 * tid];
        float m1 = (float)smk[2 * tid + 1];
        float w0 = out[TWO_N + a];
        float w1 = out[TWO_N + a + 1];
        float d = m0 + m1 + 1e-10f;
        out[TWO_N + a]      = w0 * m0 / d;
        out[TWO_N + a + 1]  = w1 * m1 / d;
        out[FOUR_N + a]     = m0;
        out[FOUR_N + a + 1] = m1;
    }
}

extern "C" void kernel_launch(void* const* d_in, const int* in_sizes, int n_in,
                              void* d_out, int out_size)
{
    const float* x = (const float*)d_in[0];
    const float* W = (const float*)d_in[1];
    if (n_in >= 2 && in_sizes[0] < in_sizes[1]) {  // safety: order by size
        const float* t = x; x = W; W = t;
    }
    float* out = (float*)d_out;

    cudaFuncSetAttribute(k1_gemm_top2,
                         cudaFuncAttributeMaxDynamicSharedMemorySize, DSM_BYTES);

    k1_gemm_top2<<<NBLK1, 256, DSM_BYTES>>>(x, W, out);
    k2_scan<<<64, 256>>>(out);
    k3_mask<<<NCHUNK, 256>>>(out);
}